// round 16
// baseline (speedup 1.0000x reference)
#include <cuda_runtime.h>
#include <cuda_bf16.h>
#include <cstdint>

// ============================ problem constants ============================
#define NROW   8192
#define NDIM   1024
#define RBLK   64          // 64 row-blocks of 128 rows
#define KST    16          // 16 K-stages of 64 bf16 (1024 total)
#define NS     3           // pipeline depth
#define TILE_B 16384       // one 128-row x 128-byte (64 bf16) tile
#define NTILES 2080        // 64*65/2 upper-triangle tiles
#define EPSF   1e-7f
#define ALPHAF 0.1f

// ============================ device scratch ===============================
__device__ __align__(1024) unsigned char g_Hb[(size_t)RBLK * KST * TILE_B]; // 16 MB pre-swizzled bf16
__device__ float g_xn[NROW];
__device__ int   g_lab[NROW];
__device__ float g_pmax [(size_t)RBLK * NROW];
__device__ float g_pmin1[(size_t)RBLK * NROW];
__device__ float g_pmin2[(size_t)RBLK * NROW];
__device__ float g_bsum[128];
__device__ float g_bcnt[128];
__device__ int   g_red_cnt;

// ============================ PTX helpers ==================================
__device__ __forceinline__ uint32_t smem_u32(const void* p){
  uint32_t a;
  asm("{ .reg .u64 t; cvta.to.shared.u64 t, %1; cvt.u32.u64 %0, t; }" : "=r"(a) : "l"(p));
  return a;
}
#define MBAR_INIT(addr, cnt) \
  asm volatile("mbarrier.init.shared.b64 [%0], %1;" :: "r"(addr), "r"(cnt) : "memory")
#define MBAR_EXPECT_TX(addr, bytes) \
  asm volatile("mbarrier.arrive.expect_tx.shared.b64 _, [%0], %1;" :: "r"(addr), "r"(bytes) : "memory")
#define MBAR_ARRIVE(addr) \
  asm volatile("mbarrier.arrive.shared.b64 _, [%0];" :: "r"(addr) : "memory")

#define MBAR_WAIT_PARITY(mbar_smem_addr, phase_parity) do { \
    uint32_t _mbar = (uint32_t)(mbar_smem_addr); \
    uint32_t _parity = (uint32_t)(phase_parity); \
    uint32_t _done; \
    asm volatile("{\n\t.reg .pred p;\n\t" \
        "mbarrier.try_wait.parity.acquire.cta.shared::cta.b64 p, [%1], %2;\n\t" \
        "selp.b32 %0, 1, 0, p;\n\t}" \
        : "=r"(_done) : "r"(_mbar), "r"(_parity) : "memory"); \
    if (!_done) { \
        asm volatile("{\n\t.reg .pred P1;\n\t" \
            "WAIT_LOOP_%=:\n\t" \
            "mbarrier.try_wait.parity.acquire.cta.shared::cta.b64 P1, [%0], %1, 0x989680;\n\t" \
            "@P1 bra.uni WAIT_DONE_%=;\n\t" \
            "bra.uni WAIT_LOOP_%=;\n\t" \
            "WAIT_DONE_%=:\n\t}" \
            :: "r"(_mbar), "r"(_parity) : "memory"); \
    } \
} while(0)

__device__ __forceinline__ void bulk_g2s(uint32_t dst, const void* src, uint32_t bytes, uint32_t mbar){
  asm volatile("cp.async.bulk.shared::cluster.global.mbarrier::complete_tx::bytes [%0], [%1], %2, [%3];"
      :: "r"(dst), "l"(src), "r"(bytes), "r"(mbar) : "memory");
}

__device__ __forceinline__ void ldsm4(uint32_t a, uint32_t& r0, uint32_t& r1, uint32_t& r2, uint32_t& r3){
  asm volatile("ldmatrix.sync.aligned.m8n8.x4.shared.b16 {%0,%1,%2,%3}, [%4];"
    : "=r"(r0), "=r"(r1), "=r"(r2), "=r"(r3) : "r"(a));
}

__device__ __forceinline__ void mma16816(float* c,
    uint32_t a0, uint32_t a1, uint32_t a2, uint32_t a3, uint32_t b0, uint32_t b1){
  asm volatile("mma.sync.aligned.m16n8k16.row.col.f32.bf16.bf16.f32 "
    "{%0,%1,%2,%3}, {%4,%5,%6,%7}, {%8,%9}, {%0,%1,%2,%3};"
    : "+f"(c[0]), "+f"(c[1]), "+f"(c[2]), "+f"(c[3])
    : "r"(a0), "r"(a1), "r"(a2), "r"(a3), "r"(b0), "r"(b1));
}

__device__ __forceinline__ void ins2(float x, float& m1, float& m2){
  if (x < m1) { m2 = m1; m1 = x; } else if (x < m2) { m2 = x; }
}

// merge {maxpos, min1, min2} triples across lanes via xor-shuffle
__device__ __forceinline__ void tri_merge(float& mp, float& m1, float& m2, int s){
  float omp = __shfl_xor_sync(0xffffffffu, mp, s);
  float om1 = __shfl_xor_sync(0xffffffffu, m1, s);
  float om2 = __shfl_xor_sync(0xffffffffu, m2, s);
  mp = fmaxf(mp, omp);
  float hi = fmaxf(m1, om1);
  m1 = fminf(m1, om1);
  m2 = fminf(fminf(m2, om2), hi);
}

// ============================ SMEM layout (GEMM) ===========================
#define SO_FULL   16        // NS full mbarriers
#define SO_EMPTY  64        // NS empty mbarriers
#define SO_RLAB   128
#define SO_CLAB   640
#define SO_RXN    1152
#define SO_CXN    1664
#define SO_STAGE  4096
#define SMEM_SZ   (4096 + NS * 32768)   // 102400 bytes; epilogue 128x129 f32 fits

// ============================ kernels ======================================

// row norms (one warp per row) + label normalization (block 0 only) + counter reset
__global__ void triplet_norm_kernel(const float* __restrict__ H,
                                    const int* __restrict__ lab32){
  int w = (blockIdx.x * blockDim.x + threadIdx.x) >> 5;
  int lane = threadIdx.x & 31;
  if (w < NROW){
    const float* row = H + (size_t)w * NDIM;
    float acc = 0.f;
    #pragma unroll
    for (int i = 0; i < NDIM/32; i++){ float v = row[lane + 32*i]; acc = fmaf(v, v, acc); }
    #pragma unroll
    for (int s = 16; s; s >>= 1) acc += __shfl_xor_sync(0xffffffffu, acc, s);
    if (!lane) g_xn[w] = acc;
  }
  // block 0: label int64/int32 detection + copy (in-bounds probe), counter reset
  if (blockIdx.x == 0){
    __shared__ int sflag;
    if (threadIdx.x == 0){ sflag = 0; g_red_cnt = 0; }
    __syncthreads();
    int acc = 0;
    for (int i = threadIdx.x; i < NROW/2; i += 256) acc |= lab32[2*i + 1];
    if (acc) atomicOr(&sflag, 1);
    __syncthreads();
    bool is64 = (sflag == 0);   // all odd words zero -> int64 payload
    for (int i = threadIdx.x; i < NROW; i += 256)
      g_lab[i] = is64 ? lab32[2*i] : lab32[i];
  }
}

// fp32 -> bf16, pre-applied SW128 swizzle, tiled [RBLK][KST] of 128 rows x 128B
__global__ void triplet_prep_kernel(const float* __restrict__ H){
  int rb = blockIdx.x, ks = blockIdx.y;
  size_t tbase = ((size_t)rb * KST + ks) * TILE_B;
  #pragma unroll
  for (int j = 0; j < 4; j++){
    int id = threadIdx.x + j * 256;        // 0..1023 : (row, 8-col group)
    int row = id >> 3, cg = id & 7;
    const float* src = H + (size_t)(rb*128 + row) * NDIM + ks*64 + cg*8;
    float4 f0 = *(const float4*)src;
    float4 f1 = *(const float4*)(src + 4);
    __nv_bfloat162 p0 = __floats2bfloat162_rn(f0.x, f0.y);
    __nv_bfloat162 p1 = __floats2bfloat162_rn(f0.z, f0.w);
    __nv_bfloat162 p2 = __floats2bfloat162_rn(f1.x, f1.y);
    __nv_bfloat162 p3 = __floats2bfloat162_rn(f1.z, f1.w);
    uint4 o;
    o.x = *reinterpret_cast<unsigned*>(&p0);
    o.y = *reinterpret_cast<unsigned*>(&p1);
    o.z = *reinterpret_cast<unsigned*>(&p2);
    o.w = *reinterpret_cast<unsigned*>(&p3);
    uint32_t off = (uint32_t)row * 128u + (uint32_t)cg * 16u;
    uint32_t sw  = off ^ ((off >> 3) & 0x70);
    *reinterpret_cast<uint4*>(g_Hb + tbase + sw) = o;
  }
}

// main fused GEMM + reduction: one 256-thread CTA per upper-triangle 128x128 tile
__global__ void __launch_bounds__(256, 2) triplet_gemm_kernel(){
  extern __shared__ __align__(1024) unsigned char smem[];
  uint32_t sb = smem_u32(smem);
  int tid = threadIdx.x, wid = tid >> 5, lane = tid & 31;

  // decode triangular tile index
  int t = blockIdx.x;
  int bi = 0, rem = t;
  while (rem >= RBLK - bi){ rem -= RBLK - bi; bi++; }
  int bj = bi + rem;

  if (tid == 0){
    #pragma unroll
    for (int s = 0; s < NS; s++){
      MBAR_INIT(sb + SO_FULL  + 8*s, 1);
      MBAR_INIT(sb + SO_EMPTY + 8*s, 8);   // one arrive per warp
    }
  }
  if (tid < 128){
    ((int*)  (smem + SO_RLAB))[tid] = g_lab[bi*128 + tid];
    ((int*)  (smem + SO_CLAB))[tid] = g_lab[bj*128 + tid];
    ((float*)(smem + SO_RXN ))[tid] = g_xn [bi*128 + tid];
    ((float*)(smem + SO_CXN ))[tid] = g_xn [bj*128 + tid];
  }
  __syncthreads();

  // producer prologue: fill all NS stages
  if (tid == 0){
    #pragma unroll
    for (int st = 0; st < NS; st++){
      uint32_t full = sb + SO_FULL + 8*st;
      MBAR_EXPECT_TX(full, 2 * TILE_B);
      uint32_t dst = sb + SO_STAGE + st * 32768;
      bulk_g2s(dst,          g_Hb + ((size_t)bi*KST + st) * TILE_B, TILE_B, full);
      bulk_g2s(dst + TILE_B, g_Hb + ((size_t)bj*KST + st) * TILE_B, TILE_B, full);
    }
  }

  // warp tiling: 2 (M) x 4 (N) warps; each warp owns 64x32 of the 128x128 tile
  int wm = wid & 1, wn = wid >> 1;
  int R0 = wm * 64, C0 = wn * 32;
  int a_row = ((lane >> 3) & 1) * 8 + (lane & 7);
  int a_kq  = (lane >> 4);
  int b_n   = ((lane >> 4) & 1) * 8 + (lane & 7);
  int b_kq  = (lane >> 3) & 1;
  // per-warp chunk rotation (measured neutral, kept: decorrelates SMSP bursts)
  int rot = ((wid & 3) + ((wid >> 2) << 1)) & 3;

  float acc[4][4][4];
  #pragma unroll
  for (int i = 0; i < 4; i++)
    #pragma unroll
    for (int j = 0; j < 4; j++)
      #pragma unroll
      for (int k = 0; k < 4; k++) acc[i][j][k] = 0.f;

  int st = 0, ph = 0;
  for (int ks = 0; ks < KST; ks++){
    MBAR_WAIT_PARITY(sb + SO_FULL + 8*st, ph);
    uint32_t bA = sb + SO_STAGE + st * 32768;
    uint32_t bB = bA + TILE_B;
    #pragma unroll
    for (int s4 = 0; s4 < 4; s4++){         // 4 x K=16 per 64-wide stage, rotated
      int kg0 = 2 * ((s4 + rot) & 3);
      uint32_t a0[4], a1[4], a2[4], a3[4];
      #pragma unroll
      for (int mt = 0; mt < 4; mt++){
        int r = R0 + mt*16 + a_row;
        int kg = kg0 + a_kq;
        uint32_t ad = bA + r*128 + ((kg ^ (r & 7)) << 4);
        ldsm4(ad, a0[mt], a1[mt], a2[mt], a3[mt]);
      }
      uint32_t bb[4][2];
      #pragma unroll
      for (int p = 0; p < 2; p++){
        int n = C0 + p*16 + b_n;
        int kg = kg0 + b_kq;
        uint32_t ad = bB + n*128 + ((kg ^ (n & 7)) << 4);
        uint32_t r0, r1, r2, r3;
        ldsm4(ad, r0, r1, r2, r3);
        bb[2*p][0] = r0; bb[2*p][1] = r1; bb[2*p+1][0] = r2; bb[2*p+1][1] = r3;
      }
      #pragma unroll
      for (int mt = 0; mt < 4; mt++)
        #pragma unroll
        for (int nt = 0; nt < 4; nt++)
          mma16816(acc[mt][nt], a0[mt], a1[mt], a2[mt], a3[mt], bb[nt][0], bb[nt][1]);
    }
    // this warp is done reading stage st
    __syncwarp();
    if (lane == 0) MBAR_ARRIVE(sb + SO_EMPTY + 8*st);
    // producer: refill stage st for iteration ks+NS once all 8 warps arrived
    if (tid == 0 && ks + NS < KST){
      MBAR_WAIT_PARITY(sb + SO_EMPTY + 8*st, ph);
      uint32_t full = sb + SO_FULL + 8*st;
      MBAR_EXPECT_TX(full, 2 * TILE_B);
      uint32_t dst = sb + SO_STAGE + st * 32768;
      int k2 = ks + NS;
      bulk_g2s(dst,          g_Hb + ((size_t)bi*KST + k2) * TILE_B, TILE_B, full);
      bulk_g2s(dst + TILE_B, g_Hb + ((size_t)bj*KST + k2) * TILE_B, TILE_B, full);
    }
    if (++st == NS){ st = 0; ph ^= 1; }
  }

  // all warps must be fully done before the epilogue tile aliases stage SMEM
  __syncthreads();

  // ---------------- epilogue ----------------
  float* sD = (float*)(smem + SO_STAGE);     // 128 x 128 padded to stride 129
  const int*   sRL = (const int*)  (smem + SO_RLAB);
  const int*   sCL = (const int*)  (smem + SO_CLAB);
  const float* sRX = (const float*)(smem + SO_RXN);
  const float* sCX = (const float*)(smem + SO_CXN);

  float xnr[8], xnc[8];
  #pragma unroll
  for (int mt = 0; mt < 4; mt++){
    xnr[2*mt]   = sRX[R0 + mt*16 + (lane >> 2)];
    xnr[2*mt+1] = sRX[R0 + mt*16 + (lane >> 2) + 8];
  }
  #pragma unroll
  for (int nt = 0; nt < 4; nt++){
    xnc[2*nt]   = sCX[C0 + nt*8 + 2*(lane & 3)];
    xnc[2*nt+1] = sCX[C0 + nt*8 + 2*(lane & 3) + 1];
  }
  #pragma unroll
  for (int mt = 0; mt < 4; mt++)
    #pragma unroll
    for (int nt = 0; nt < 4; nt++)
      #pragma unroll
      for (int h = 0; h < 2; h++)
        #pragma unroll
        for (int o = 0; o < 2; o++){
          float g = acc[mt][nt][2*h + o];
          int r = R0 + mt*16 + (lane >> 2) + 8*h;
          int c = C0 + nt*8  + 2*(lane & 3) + o;
          float d = fmaf(-2.f, g, xnr[2*mt + h] + xnc[2*nt + o]);
          d = fmaxf(d, EPSF);                 // also squashes NaN, matches ref
          sD[r*129 + c] = d;
        }
  __syncthreads();

  if (tid < 128){
    // row pass: anchor = bi*128 + r, column block bj
    int r = tid;
    int rl = sRL[r];
    float mp = 0.f, m1 = 3.0e38f, m2 = 3.0e38f;
    #pragma unroll 4
    for (int c = 0; c < 128; c++){
      float d = sD[r*129 + c];
      bool same = (sCL[c] == rl);
      bool diag = (bi == bj) && (c == r);
      if (same){ if (!diag) mp = fmaxf(mp, d); }
      else ins2(d, m1, m2);
    }
    size_t o = (size_t)bj * NROW + (size_t)bi * 128 + r;
    g_pmax[o] = mp; g_pmin1[o] = m1; g_pmin2[o] = m2;
  } else if (bi != bj){
    // column pass: anchor = bj*128 + c, column block bi
    int c = tid - 128;
    int cl = sCL[c];
    float mp = 0.f, m1 = 3.0e38f, m2 = 3.0e38f;
    #pragma unroll 4
    for (int rr = 0; rr < 128; rr++){
      float d = sD[rr*129 + c];
      if (sRL[rr] == cl) mp = fmaxf(mp, d);
      else ins2(d, m1, m2);
    }
    size_t o = (size_t)bi * NROW + (size_t)bj * 128 + c;
    g_pmax[o] = mp; g_pmin1[o] = m1; g_pmin2[o] = m2;
  }
}

// merge the 64 column-block partials per anchor: 128 CTAs, 4 lanes per anchor.
// Last block folds the 128 block partials and writes the output.
__global__ void triplet_reduce1(float* __restrict__ out){
  int tid = threadIdx.x;
  int a   = blockIdx.x * 64 + (tid >> 2);   // anchor
  int seg = tid & 3;                        // 16-slot segment
  float hp = 0.f, m1 = 3.0e38f, m2 = 3.0e38f;
  #pragma unroll 4
  for (int i = 0; i < 16; i++){
    int cb = seg * 16 + i;
    size_t o = (size_t)cb * NROW + a;
    hp = fmaxf(hp, g_pmax[o]);
    ins2(g_pmin1[o], m1, m2);
    ins2(g_pmin2[o], m1, m2);
  }
  tri_merge(hp, m1, m2, 1);
  tri_merge(hp, m1, m2, 2);
  float loss = fmaxf(hp - m2 + ALPHAF, 0.f);
  float rel  = (loss > EPSF) ? 1.f : 0.f;
  float v = (seg == 0) ? rel * loss : 0.f;
  float c = (seg == 0) ? rel : 0.f;

  __shared__ float ss[256], sc[256];
  __shared__ int slast;
  ss[tid] = v; sc[tid] = c;
  __syncthreads();
  for (int s = 128; s; s >>= 1){
    if (tid < s){ ss[tid] += ss[tid + s]; sc[tid] += sc[tid + s]; }
    __syncthreads();
  }
  if (!tid){
    g_bsum[blockIdx.x] = ss[0];
    g_bcnt[blockIdx.x] = sc[0];
    __threadfence();
    int old = atomicAdd(&g_red_cnt, 1);
    slast = (old == 127) ? 1 : 0;
  }
  __syncthreads();
  if (slast && tid < 32){
    float s = 0.f, cc = 0.f;
    #pragma unroll
    for (int k = 0; k < 4; k++){ s += g_bsum[tid + 32*k]; cc += g_bcnt[tid + 32*k]; }
    #pragma unroll
    for (int k = 16; k; k >>= 1){
      s  += __shfl_xor_sync(0xffffffffu, s,  k);
      cc += __shfl_xor_sync(0xffffffffu, cc, k);
    }
    if (!tid) out[0] = s / cc;
  }
}

// ============================ launch =======================================
extern "C" void kernel_launch(void* const* d_in, const int* in_sizes, int n_in,
                              void* d_out, int out_size){
  const float* H   = (const float*)d_in[0];
  const int*   lab = (const int*)  d_in[1];
  float* out = (float*)d_out;

  cudaFuncSetAttribute(triplet_gemm_kernel,
                       cudaFuncAttributeMaxDynamicSharedMemorySize, SMEM_SZ);

  triplet_norm_kernel<<<1024, 256>>>(H, lab);
  triplet_prep_kernel<<<dim3(RBLK, KST), 256>>>(H);
  triplet_gemm_kernel<<<NTILES, 256, SMEM_SZ>>>();
  triplet_reduce1    <<<128, 256>>>(out);
}

// round 17
// speedup vs baseline: 1.5430x; 1.5430x over previous
#include <cuda_runtime.h>
#include <cuda_bf16.h>
#include <cstdint>

// ============================ problem constants ============================
#define NROW   8192
#define NDIM   1024
#define RBLK   64          // 64 row-blocks of 128 rows
#define KST    16          // 16 K-stages of 64 bf16 (1024 total)
#define NS     3           // pipeline depth
#define TILE_B 16384       // one 128-row x 128-byte (64 bf16) tile
#define NTILES 2080        // 64*65/2 upper-triangle tiles
#define EPSF   1e-7f
#define ALPHAF 0.1f

// ============================ device scratch ===============================
__device__ __align__(1024) unsigned char g_Hb[(size_t)RBLK * KST * TILE_B]; // 16 MB pre-swizzled bf16
__device__ float g_xn[NROW];
__device__ int   g_lab[NROW];
__device__ float g_pmax [(size_t)RBLK * NROW];
__device__ float g_pmin1[(size_t)RBLK * NROW];
__device__ float g_pmin2[(size_t)RBLK * NROW];
__device__ float g_bsum[128];
__device__ float g_bcnt[128];
__device__ int   g_red_cnt;

// ============================ PTX helpers ==================================
__device__ __forceinline__ uint32_t smem_u32(const void* p){
  uint32_t a;
  asm("{ .reg .u64 t; cvta.to.shared.u64 t, %1; cvt.u32.u64 %0, t; }" : "=r"(a) : "l"(p));
  return a;
}
#define MBAR_INIT(addr, cnt) \
  asm volatile("mbarrier.init.shared.b64 [%0], %1;" :: "r"(addr), "r"(cnt) : "memory")
#define MBAR_EXPECT_TX(addr, bytes) \
  asm volatile("mbarrier.arrive.expect_tx.shared.b64 _, [%0], %1;" :: "r"(addr), "r"(bytes) : "memory")
#define MBAR_ARRIVE(addr) \
  asm volatile("mbarrier.arrive.shared.b64 _, [%0];" :: "r"(addr) : "memory")

#define MBAR_WAIT_PARITY(mbar_smem_addr, phase_parity) do { \
    uint32_t _mbar = (uint32_t)(mbar_smem_addr); \
    uint32_t _parity = (uint32_t)(phase_parity); \
    uint32_t _done; \
    asm volatile("{\n\t.reg .pred p;\n\t" \
        "mbarrier.try_wait.parity.acquire.cta.shared::cta.b64 p, [%1], %2;\n\t" \
        "selp.b32 %0, 1, 0, p;\n\t}" \
        : "=r"(_done) : "r"(_mbar), "r"(_parity) : "memory"); \
    if (!_done) { \
        asm volatile("{\n\t.reg .pred P1;\n\t" \
            "WAIT_LOOP_%=:\n\t" \
            "mbarrier.try_wait.parity.acquire.cta.shared::cta.b64 P1, [%0], %1, 0x989680;\n\t" \
            "@P1 bra.uni WAIT_DONE_%=;\n\t" \
            "bra.uni WAIT_LOOP_%=;\n\t" \
            "WAIT_DONE_%=:\n\t}" \
            :: "r"(_mbar), "r"(_parity) : "memory"); \
    } \
} while(0)

__device__ __forceinline__ void bulk_g2s(uint32_t dst, const void* src, uint32_t bytes, uint32_t mbar){
  asm volatile("cp.async.bulk.shared::cluster.global.mbarrier::complete_tx::bytes [%0], [%1], %2, [%3];"
      :: "r"(dst), "l"(src), "r"(bytes), "r"(mbar) : "memory");
}

__device__ __forceinline__ void ldsm4(uint32_t a, uint32_t& r0, uint32_t& r1, uint32_t& r2, uint32_t& r3){
  asm volatile("ldmatrix.sync.aligned.m8n8.x4.shared.b16 {%0,%1,%2,%3}, [%4];"
    : "=r"(r0), "=r"(r1), "=r"(r2), "=r"(r3) : "r"(a));
}

__device__ __forceinline__ void mma16816(float* c,
    uint32_t a0, uint32_t a1, uint32_t a2, uint32_t a3, uint32_t b0, uint32_t b1){
  asm volatile("mma.sync.aligned.m16n8k16.row.col.f32.bf16.bf16.f32 "
    "{%0,%1,%2,%3}, {%4,%5,%6,%7}, {%8,%9}, {%0,%1,%2,%3};"
    : "+f"(c[0]), "+f"(c[1]), "+f"(c[2]), "+f"(c[3])
    : "r"(a0), "r"(a1), "r"(a2), "r"(a3), "r"(b0), "r"(b1));
}

__device__ __forceinline__ void ins2(float x, float& m1, float& m2){
  if (x < m1) { m2 = m1; m1 = x; } else if (x < m2) { m2 = x; }
}

// merge {maxpos, min1, min2} triples across lanes via xor-shuffle
__device__ __forceinline__ void tri_merge(float& mp, float& m1, float& m2, int s){
  float omp = __shfl_xor_sync(0xffffffffu, mp, s);
  float om1 = __shfl_xor_sync(0xffffffffu, m1, s);
  float om2 = __shfl_xor_sync(0xffffffffu, m2, s);
  mp = fmaxf(mp, omp);
  float hi = fmaxf(m1, om1);
  m1 = fminf(m1, om1);
  m2 = fminf(fminf(m2, om2), hi);
}

// ============================ SMEM layout (GEMM) ===========================
#define SO_FULL   16        // NS full mbarriers
#define SO_EMPTY  64        // NS empty mbarriers
#define SO_RLAB   128
#define SO_CLAB   640
#define SO_RXN    1152
#define SO_CXN    1664
#define SO_STAGE  4096
#define SMEM_SZ   (4096 + NS * 32768)   // 102400 bytes; epilogue 128x129 f32 fits

// ============================ kernels ======================================

// row norms (one warp per row) + label normalization (block 0 only) + counter reset
__global__ void triplet_norm_kernel(const float* __restrict__ H,
                                    const int* __restrict__ lab32){
  int w = (blockIdx.x * blockDim.x + threadIdx.x) >> 5;
  int lane = threadIdx.x & 31;
  if (w < NROW){
    const float* row = H + (size_t)w * NDIM;
    float acc = 0.f;
    #pragma unroll
    for (int i = 0; i < NDIM/32; i++){ float v = row[lane + 32*i]; acc = fmaf(v, v, acc); }
    #pragma unroll
    for (int s = 16; s; s >>= 1) acc += __shfl_xor_sync(0xffffffffu, acc, s);
    if (!lane) g_xn[w] = acc;
  }
  // block 0: label int64/int32 detection + copy (in-bounds probe), counter reset
  if (blockIdx.x == 0){
    __shared__ int sflag;
    if (threadIdx.x == 0){ sflag = 0; g_red_cnt = 0; }
    __syncthreads();
    int acc = 0;
    for (int i = threadIdx.x; i < NROW/2; i += 256) acc |= lab32[2*i + 1];
    if (acc) atomicOr(&sflag, 1);
    __syncthreads();
    bool is64 = (sflag == 0);   // all odd words zero -> int64 payload
    for (int i = threadIdx.x; i < NROW; i += 256)
      g_lab[i] = is64 ? lab32[2*i] : lab32[i];
  }
}

// fp32 -> bf16, pre-applied SW128 swizzle, tiled [RBLK][KST] of 128 rows x 128B
__global__ void triplet_prep_kernel(const float* __restrict__ H){
  int rb = blockIdx.x, ks = blockIdx.y;
  size_t tbase = ((size_t)rb * KST + ks) * TILE_B;
  #pragma unroll
  for (int j = 0; j < 4; j++){
    int id = threadIdx.x + j * 256;        // 0..1023 : (row, 8-col group)
    int row = id >> 3, cg = id & 7;
    const float* src = H + (size_t)(rb*128 + row) * NDIM + ks*64 + cg*8;
    float4 f0 = *(const float4*)src;
    float4 f1 = *(const float4*)(src + 4);
    __nv_bfloat162 p0 = __floats2bfloat162_rn(f0.x, f0.y);
    __nv_bfloat162 p1 = __floats2bfloat162_rn(f0.z, f0.w);
    __nv_bfloat162 p2 = __floats2bfloat162_rn(f1.x, f1.y);
    __nv_bfloat162 p3 = __floats2bfloat162_rn(f1.z, f1.w);
    uint4 o;
    o.x = *reinterpret_cast<unsigned*>(&p0);
    o.y = *reinterpret_cast<unsigned*>(&p1);
    o.z = *reinterpret_cast<unsigned*>(&p2);
    o.w = *reinterpret_cast<unsigned*>(&p3);
    uint32_t off = (uint32_t)row * 128u + (uint32_t)cg * 16u;
    uint32_t sw  = off ^ ((off >> 3) & 0x70);
    *reinterpret_cast<uint4*>(g_Hb + tbase + sw) = o;
  }
}

// main fused GEMM + reduction: one 256-thread CTA per upper-triangle 128x128 tile
__global__ void __launch_bounds__(256, 2) triplet_gemm_kernel(){
  extern __shared__ __align__(1024) unsigned char smem[];
  uint32_t sb = smem_u32(smem);
  int tid = threadIdx.x, wid = tid >> 5, lane = tid & 31;

  // decode triangular tile index
  int t = blockIdx.x;
  int bi = 0, rem = t;
  while (rem >= RBLK - bi){ rem -= RBLK - bi; bi++; }
  int bj = bi + rem;

  if (tid == 0){
    #pragma unroll
    for (int s = 0; s < NS; s++){
      MBAR_INIT(sb + SO_FULL  + 8*s, 1);
      MBAR_INIT(sb + SO_EMPTY + 8*s, 8);   // one arrive per warp
    }
  }
  if (tid < 128){
    ((int*)  (smem + SO_RLAB))[tid] = g_lab[bi*128 + tid];
    ((int*)  (smem + SO_CLAB))[tid] = g_lab[bj*128 + tid];
    ((float*)(smem + SO_RXN ))[tid] = g_xn [bi*128 + tid];
    ((float*)(smem + SO_CXN ))[tid] = g_xn [bj*128 + tid];
  }
  __syncthreads();

  // producer prologue: fill all NS stages
  if (tid == 0){
    #pragma unroll
    for (int st = 0; st < NS; st++){
      uint32_t full = sb + SO_FULL + 8*st;
      MBAR_EXPECT_TX(full, 2 * TILE_B);
      uint32_t dst = sb + SO_STAGE + st * 32768;
      bulk_g2s(dst,          g_Hb + ((size_t)bi*KST + st) * TILE_B, TILE_B, full);
      bulk_g2s(dst + TILE_B, g_Hb + ((size_t)bj*KST + st) * TILE_B, TILE_B, full);
    }
  }

  // warp tiling: 2 (M) x 4 (N) warps; each warp owns 64x32 of the 128x128 tile
  int wm = wid & 1, wn = wid >> 1;
  int R0 = wm * 64, C0 = wn * 32;
  int a_row = ((lane >> 3) & 1) * 8 + (lane & 7);
  int a_kq  = (lane >> 4);
  int b_n   = ((lane >> 4) & 1) * 8 + (lane & 7);
  int b_kq  = (lane >> 3) & 1;
  // per-warp chunk rotation (measured neutral, kept: decorrelates SMSP bursts)
  int rot = ((wid & 3) + ((wid >> 2) << 1)) & 3;

  float acc[4][4][4];
  #pragma unroll
  for (int i = 0; i < 4; i++)
    #pragma unroll
    for (int j = 0; j < 4; j++)
      #pragma unroll
      for (int k = 0; k < 4; k++) acc[i][j][k] = 0.f;

  int st = 0, ph = 0;
  for (int ks = 0; ks < KST; ks++){
    MBAR_WAIT_PARITY(sb + SO_FULL + 8*st, ph);
    uint32_t bA = sb + SO_STAGE + st * 32768;
    uint32_t bB = bA + TILE_B;
    #pragma unroll
    for (int s4 = 0; s4 < 4; s4++){         // 4 x K=16 per 64-wide stage, rotated
      int kg0 = 2 * ((s4 + rot) & 3);
      uint32_t a0[4], a1[4], a2[4], a3[4];
      #pragma unroll
      for (int mt = 0; mt < 4; mt++){
        int r = R0 + mt*16 + a_row;
        int kg = kg0 + a_kq;
        uint32_t ad = bA + r*128 + ((kg ^ (r & 7)) << 4);
        ldsm4(ad, a0[mt], a1[mt], a2[mt], a3[mt]);
      }
      uint32_t bb[4][2];
      #pragma unroll
      for (int p = 0; p < 2; p++){
        int n = C0 + p*16 + b_n;
        int kg = kg0 + b_kq;
        uint32_t ad = bB + n*128 + ((kg ^ (n & 7)) << 4);
        uint32_t r0, r1, r2, r3;
        ldsm4(ad, r0, r1, r2, r3);
        bb[2*p][0] = r0; bb[2*p][1] = r1; bb[2*p+1][0] = r2; bb[2*p+1][1] = r3;
      }
      #pragma unroll
      for (int mt = 0; mt < 4; mt++)
        #pragma unroll
        for (int nt = 0; nt < 4; nt++)
          mma16816(acc[mt][nt], a0[mt], a1[mt], a2[mt], a3[mt], bb[nt][0], bb[nt][1]);
    }
    // this warp is done reading stage st
    __syncwarp();
    if (lane == 0) MBAR_ARRIVE(sb + SO_EMPTY + 8*st);
    // producer: refill stage st for iteration ks+NS once all 8 warps arrived
    if (tid == 0 && ks + NS < KST){
      MBAR_WAIT_PARITY(sb + SO_EMPTY + 8*st, ph);
      uint32_t full = sb + SO_FULL + 8*st;
      MBAR_EXPECT_TX(full, 2 * TILE_B);
      uint32_t dst = sb + SO_STAGE + st * 32768;
      int k2 = ks + NS;
      bulk_g2s(dst,          g_Hb + ((size_t)bi*KST + k2) * TILE_B, TILE_B, full);
      bulk_g2s(dst + TILE_B, g_Hb + ((size_t)bj*KST + k2) * TILE_B, TILE_B, full);
    }
    if (++st == NS){ st = 0; ph ^= 1; }
  }

  // all warps must be fully done before the epilogue tile aliases stage SMEM
  __syncthreads();

  // ---------------- epilogue ----------------
  float* sD = (float*)(smem + SO_STAGE);     // 128 x 128 padded to stride 129
  const int*   sRL = (const int*)  (smem + SO_RLAB);
  const int*   sCL = (const int*)  (smem + SO_CLAB);
  const float* sRX = (const float*)(smem + SO_RXN);
  const float* sCX = (const float*)(smem + SO_CXN);

  float xnr[8], xnc[8];
  #pragma unroll
  for (int mt = 0; mt < 4; mt++){
    xnr[2*mt]   = sRX[R0 + mt*16 + (lane >> 2)];
    xnr[2*mt+1] = sRX[R0 + mt*16 + (lane >> 2) + 8];
  }
  #pragma unroll
  for (int nt = 0; nt < 4; nt++){
    xnc[2*nt]   = sCX[C0 + nt*8 + 2*(lane & 3)];
    xnc[2*nt+1] = sCX[C0 + nt*8 + 2*(lane & 3) + 1];
  }
  #pragma unroll
  for (int mt = 0; mt < 4; mt++)
    #pragma unroll
    for (int nt = 0; nt < 4; nt++)
      #pragma unroll
      for (int h = 0; h < 2; h++)
        #pragma unroll
        for (int o = 0; o < 2; o++){
          float g = acc[mt][nt][2*h + o];
          int r = R0 + mt*16 + (lane >> 2) + 8*h;
          int c = C0 + nt*8  + 2*(lane & 3) + o;
          float d = fmaf(-2.f, g, xnr[2*mt + h] + xnc[2*nt + o]);
          d = fmaxf(d, EPSF);                 // also squashes NaN, matches ref
          sD[r*129 + c] = d;
        }
  __syncthreads();

  if (tid < 128){
    // row pass: anchor = bi*128 + r, column block bj
    int r = tid;
    int rl = sRL[r];
    float mp = 0.f, m1 = 3.0e38f, m2 = 3.0e38f;
    #pragma unroll 4
    for (int c = 0; c < 128; c++){
      float d = sD[r*129 + c];
      bool same = (sCL[c] == rl);
      bool diag = (bi == bj) && (c == r);
      if (same){ if (!diag) mp = fmaxf(mp, d); }
      else ins2(d, m1, m2);
    }
    size_t o = (size_t)bj * NROW + (size_t)bi * 128 + r;
    g_pmax[o] = mp; g_pmin1[o] = m1; g_pmin2[o] = m2;
  } else if (bi != bj){
    // column pass: anchor = bj*128 + c, column block bi
    int c = tid - 128;
    int cl = sCL[c];
    float mp = 0.f, m1 = 3.0e38f, m2 = 3.0e38f;
    #pragma unroll 4
    for (int rr = 0; rr < 128; rr++){
      float d = sD[rr*129 + c];
      if (sRL[rr] == cl) mp = fmaxf(mp, d);
      else ins2(d, m1, m2);
    }
    size_t o = (size_t)bi * NROW + (size_t)bj * 128 + c;
    g_pmax[o] = mp; g_pmin1[o] = m1; g_pmin2[o] = m2;
  }
}

// merge the 64 column-block partials per anchor: 128 CTAs, 4 lanes per anchor.
// Last block folds the 128 block partials and writes the output.
__global__ void triplet_reduce1(float* __restrict__ out){
  int tid = threadIdx.x;
  int a   = blockIdx.x * 64 + (tid >> 2);   // anchor
  int seg = tid & 3;                        // 16-slot segment
  float hp = 0.f, m1 = 3.0e38f, m2 = 3.0e38f;
  #pragma unroll 4
  for (int i = 0; i < 16; i++){
    int cb = seg * 16 + i;
    size_t o = (size_t)cb * NROW + a;
    hp = fmaxf(hp, g_pmax[o]);
    ins2(g_pmin1[o], m1, m2);
    ins2(g_pmin2[o], m1, m2);
  }
  tri_merge(hp, m1, m2, 1);
  tri_merge(hp, m1, m2, 2);
  float loss = fmaxf(hp - m2 + ALPHAF, 0.f);
  float rel  = (loss > EPSF) ? 1.f : 0.f;
  float v = (seg == 0) ? rel * loss : 0.f;
  float c = (seg == 0) ? rel : 0.f;

  __shared__ float ss[256], sc[256];
  __shared__ int slast;
  ss[tid] = v; sc[tid] = c;
  __syncthreads();
  for (int s = 128; s; s >>= 1){
    if (tid < s){ ss[tid] += ss[tid + s]; sc[tid] += sc[tid + s]; }
    __syncthreads();
  }
  if (!tid){
    g_bsum[blockIdx.x] = ss[0];
    g_bcnt[blockIdx.x] = sc[0];
    __threadfence();
    int old = atomicAdd(&g_red_cnt, 1);
    slast = (old == 127) ? 1 : 0;
  }
  __syncthreads();
  if (slast && tid < 32){
    float s = 0.f, cc = 0.f;
    #pragma unroll
    for (int k = 0; k < 4; k++){ s += g_bsum[tid + 32*k]; cc += g_bcnt[tid + 32*k]; }
    #pragma unroll
    for (int k = 16; k; k >>= 1){
      s  += __shfl_xor_sync(0xffffffffu, s,  k);
      cc += __shfl_xor_sync(0xffffffffu, cc, k);
    }
    if (!tid) out[0] = s / cc;
  }
}

// ============================ launch =======================================
extern "C" void kernel_launch(void* const* d_in, const int* in_sizes, int n_in,
                              void* d_out, int out_size){
  const float* H   = (const float*)d_in[0];
  const int*   lab = (const int*)  d_in[1];
  float* out = (float*)d_out;

  cudaFuncSetAttribute(triplet_gemm_kernel,
                       cudaFuncAttributeMaxDynamicSharedMemorySize, SMEM_SZ);

  triplet_norm_kernel<<<1024, 256>>>(H, lab);
  triplet_prep_kernel<<<dim3(RBLK, KST), 256>>>(H);
  triplet_gemm_kernel<<<NTILES, 256, SMEM_SZ>>>();
  triplet_reduce1    <<<128, 256>>>(out);
}